// round 3
// baseline (speedup 1.0000x reference)
#include <cuda_runtime.h>
#include <math.h>

#define B 32
#define S 4096
#define D 512
#define CPB 32            // chunks per batch (S split)
#define CHUNK 128         // S / CPB
#define K2_WARPS 8
#define PPW 16            // positions per warp = CHUNK / K2_WARPS
#define NEG_BIG (-1e30f)

// ---------------- scratch (no allocations allowed) ----------------
__device__ float g_ht[B * D];            // h_t = source @ W_in^T
__device__ float g_scores[B * S];        // raw (unnormalized) scores
__device__ float g_pm[B * CPB];          // per-chunk max
__device__ float g_pl[B * CPB];          // per-chunk exp-sum (rel. to chunk max)
__device__ float g_pc[B * CPB * D];      // per-chunk weighted context partial
__device__ float g_cf[B * D];            // final context vector c

// memory_lengths may arrive as int32 (JAX x64 disabled) or int64.
// lengths are in [S/2, S]; an int64 view of element 0 is in-range iff data is int64.
__device__ __forceinline__ int get_len(const void* p, int b) {
    long long v0 = ((const long long*)p)[0];
    if (v0 >= 0 && v0 <= (long long)S) return (int)((const long long*)p)[b];
    return ((const int*)p)[b];
}

__device__ __forceinline__ float warp_sum(float v) {
#pragma unroll
    for (int o = 16; o; o >>= 1) v += __shfl_xor_sync(0xffffffffu, v, o);
    return v;
}

__device__ __forceinline__ float dot4(float4 a, float4 b) {
    return fmaf(a.x, b.x, fmaf(a.y, b.y, fmaf(a.z, b.z, a.w * b.w)));
}

// ---------------- K1: h_t[b,o] = sum_k source[b,k] * W_in[o,k] ----------------
__global__ __launch_bounds__(256) void k1_ht(const float* __restrict__ src,
                                             const float* __restrict__ Win) {
    int b = blockIdx.x, t = threadIdx.x, wid = t >> 5, lane = t & 31;
    __shared__ float ssrc[D];
    ssrc[t] = src[b * D + t];
    ssrc[t + 256] = src[b * D + t + 256];
    __syncthreads();
    const float4* s4 = (const float4*)ssrc;
    float4 sv0 = s4[lane], sv1 = s4[lane + 32], sv2 = s4[lane + 64], sv3 = s4[lane + 96];
    const float4* W4 = (const float4*)Win;
    for (int o = wid; o < D; o += 8) {
        const float4* r = W4 + (size_t)o * 128 + lane;
        float p = dot4(r[0], sv0) + dot4(r[32], sv1) + dot4(r[64], sv2) + dot4(r[96], sv3);
        p = warp_sum(p);
        if (lane == 0) g_ht[b * D + o] = p;
    }
}

// ---------------- K2: single pass over memory_bank: scores + online softmax + c partials
__global__ __launch_bounds__(256) void k2_stream(const float* __restrict__ mb,
                                                 const void* __restrict__ lens) {
    int chunk = blockIdx.x, b = blockIdx.y;
    int t = threadIdx.x, wid = t >> 5, lane = t & 31;
    int len = get_len(lens, b);
    int s0 = chunk * CHUNK + wid * PPW;

    // h_t for this batch, register-resident (per-lane slice)
    const float4* h4 = (const float4*)(g_ht + b * D);
    float4 h0 = h4[lane], h1 = h4[lane + 32], h2 = h4[lane + 64], h3 = h4[lane + 96];

    float m = NEG_BIG, l = 0.f;
    float4 c0 = {0, 0, 0, 0}, c1 = {0, 0, 0, 0}, c2 = {0, 0, 0, 0}, c3 = {0, 0, 0, 0};

    int nv = len - s0;
    nv = nv < 0 ? 0 : (nv > PPW ? PPW : nv);

    const float4* r = (const float4*)mb + ((size_t)b * S + s0) * 128 + lane;
    if (nv > 0) {
        float4 a0 = r[0], a1 = r[32], a2 = r[64], a3 = r[96];
        for (int i = 0; i < nv; i++) {
            float4 v0 = a0, v1 = a1, v2 = a2, v3 = a3;
            if (i + 1 < nv) {  // prefetch next row
                const float4* rn = r + (size_t)(i + 1) * 128;
                a0 = rn[0]; a1 = rn[32]; a2 = rn[64]; a3 = rn[96];
            }
            float p = dot4(v0, h0) + dot4(v1, h1) + dot4(v2, h2) + dot4(v3, h3);
            float sc = warp_sum(p);
            if (lane == 0) g_scores[b * S + s0 + i] = sc;
            float mn = fmaxf(m, sc);
            float scale = __expf(m - mn);
            float w = __expf(sc - mn);
            l = fmaf(l, scale, w);
            c0.x = fmaf(w, v0.x, scale * c0.x); c0.y = fmaf(w, v0.y, scale * c0.y);
            c0.z = fmaf(w, v0.z, scale * c0.z); c0.w = fmaf(w, v0.w, scale * c0.w);
            c1.x = fmaf(w, v1.x, scale * c1.x); c1.y = fmaf(w, v1.y, scale * c1.y);
            c1.z = fmaf(w, v1.z, scale * c1.z); c1.w = fmaf(w, v1.w, scale * c1.w);
            c2.x = fmaf(w, v2.x, scale * c2.x); c2.y = fmaf(w, v2.y, scale * c2.y);
            c2.z = fmaf(w, v2.z, scale * c2.z); c2.w = fmaf(w, v2.w, scale * c2.w);
            c3.x = fmaf(w, v3.x, scale * c3.x); c3.y = fmaf(w, v3.y, scale * c3.y);
            c3.z = fmaf(w, v3.z, scale * c3.z); c3.w = fmaf(w, v3.w, scale * c3.w);
            m = mn;
        }
    }
    // masked tail: sentinel scores (normalizer turns these into exact 0)
    for (int j = nv + lane; j < PPW; j += 32)
        g_scores[b * S + s0 + j] = NEG_BIG;

    // ---- block-level merge of the 8 warps (no atomics) ----
    __shared__ float sm_m[K2_WARPS], sm_l[K2_WARPS], sm_f[K2_WARPS];
    __shared__ float sm_c[K2_WARPS * D];  // 16 KB
    if (lane == 0) { sm_m[wid] = m; sm_l[wid] = l; }
    float4* cw = (float4*)(sm_c + wid * D);
    cw[lane] = c0; cw[lane + 32] = c1; cw[lane + 64] = c2; cw[lane + 96] = c3;
    __syncthreads();
    if (t == 0) {
        float Mb = NEG_BIG;
#pragma unroll
        for (int w2 = 0; w2 < K2_WARPS; w2++) Mb = fmaxf(Mb, sm_m[w2]);
        float Lb = 0.f;
#pragma unroll
        for (int w2 = 0; w2 < K2_WARPS; w2++) {
            float f = __expf(sm_m[w2] - Mb);
            sm_f[w2] = f;
            Lb = fmaf(sm_l[w2], f, Lb);
        }
        g_pm[b * CPB + chunk] = Mb;
        g_pl[b * CPB + chunk] = Lb;
    }
    __syncthreads();
    for (int d = t; d < D; d += 256) {
        float acc = 0.f;
#pragma unroll
        for (int w2 = 0; w2 < K2_WARPS; w2++) acc = fmaf(sm_f[w2], sm_c[w2 * D + d], acc);
        g_pc[((size_t)b * CPB + chunk) * D + d] = acc;
    }
}

// ---------------- K3: merge chunk partials -> c; write normalized align output
__global__ __launch_bounds__(256) void k3_merge(float* __restrict__ out) {
    int b = blockIdx.x, t = threadIdx.x;
    __shared__ float sf[CPB];   // becomes per-chunk factor exp(m_i - M)
    __shared__ float sM, sInvL;
    if (t < CPB) sf[t] = g_pm[b * CPB + t];
    __syncthreads();
    if (t == 0) {
        float M = NEG_BIG;
        for (int i = 0; i < CPB; i++) M = fmaxf(M, sf[i]);
        float L = 0.f;
        for (int i = 0; i < CPB; i++) {
            float f = __expf(sf[i] - M);
            sf[i] = f;
            L = fmaf(g_pl[b * CPB + i], f, L);
        }
        sM = M;
        sInvL = 1.f / L;
    }
    __syncthreads();
    float M = sM, invL = sInvL;
    for (int d = t; d < D; d += 256) {
        float acc = 0.f;
#pragma unroll
        for (int i = 0; i < CPB; i++) acc = fmaf(sf[i], g_pc[((size_t)b * CPB + i) * D + d], acc);
        g_cf[b * D + d] = acc * invL;
    }
    float* oal = out + B * D + (size_t)b * S;  // align_vectors output
    for (int s = t; s < S; s += 256)
        oal[s] = __expf(g_scores[b * S + s] - M) * invL;
}

// ---------------- K4: attn_h[b,o] = [c, source] . W_out[o,:] ----------------
__global__ __launch_bounds__(256) void k4_out(const float* __restrict__ src,
                                              const float* __restrict__ Wout,
                                              float* __restrict__ out) {
    int b = blockIdx.x, t = threadIdx.x, wid = t >> 5, lane = t & 31;
    __shared__ float cat[D * 2];
    cat[t] = g_cf[b * D + t];
    cat[t + 256] = g_cf[b * D + t + 256];
    cat[512 + t] = src[b * D + t];
    cat[768 + t] = src[b * D + t + 256];
    __syncthreads();
    const float4* c4 = (const float4*)cat;
    float4 cv[8];
#pragma unroll
    for (int j = 0; j < 8; j++) cv[j] = c4[lane + j * 32];
    const float4* W4 = (const float4*)Wout;
    for (int o = wid; o < D; o += 8) {
        const float4* r = W4 + (size_t)o * 256 + lane;
        float p = 0.f;
#pragma unroll
        for (int j = 0; j < 8; j++) p += dot4(r[j * 32], cv[j]);
        p = warp_sum(p);
        if (lane == 0) out[b * D + o] = p;
    }
}

extern "C" void kernel_launch(void* const* d_in, const int* in_sizes, int n_in,
                              void* d_out, int out_size) {
    const float* src  = (const float*)d_in[0];  // source [B,1,D]
    const float* mb   = (const float*)d_in[1];  // memory_bank [B,S,D]
    const void*  lens = d_in[2];                // memory_lengths [B] (int32 or int64)
    const float* Win  = (const float*)d_in[3];  // [D, D]
    const float* Wout = (const float*)d_in[4];  // [D, 2D]
    float* out = (float*)d_out;                 // [B*D attn_h | B*S align]

    k1_ht<<<B, 256>>>(src, Win);
    dim3 g2(CPB, B);
    k2_stream<<<g2, 256>>>(mb, lens);
    k3_merge<<<B, 256>>>(out);
    k4_out<<<B, 256>>>(src, Wout, out);
}

// round 4
// speedup vs baseline: 2.9606x; 2.9606x over previous
#include <cuda_runtime.h>
#include <math.h>

#define B 32
#define S 4096
#define D 512
#define CPB 32            // chunks per batch
#define CHUNK 128         // S / CPB
#define K2_WARPS 8
#define PPW 16            // rows per warp in k2
#define NEG_BIG (-1e30f)

// ---------------- scratch (no allocations allowed) ----------------
__device__ float g_ht[B * D];            // h_t = source @ W_in^T
__device__ float g_scores[B * S];        // raw (unnormalized) scores
__device__ float g_pm[B * CPB];          // per-chunk max
__device__ float g_pl[B * CPB];          // per-chunk exp-sum (rel. to chunk max)
__device__ float g_pc[B * CPB * D];      // per-chunk weighted context partial
__device__ float g_cat[B * 2 * D];       // [c | source] concat per batch
__device__ float g_fac[B * CPB];         // per-chunk softmax merge factor
__device__ float g_stat[B * 2];          // per-batch {M, 1/L}

// memory_lengths may arrive as int32 (JAX x64 off) or int64.
// lengths in [S/2, S]; int64 view of elem 0 is in-range iff data truly int64.
__device__ __forceinline__ int get_len(const void* p, int b) {
    long long v0 = ((const long long*)p)[0];
    if (v0 >= 0 && v0 <= (long long)S) return (int)((const long long*)p)[b];
    return ((const int*)p)[b];
}

__device__ __forceinline__ float warp_sum(float v) {
#pragma unroll
    for (int o = 16; o; o >>= 1) v += __shfl_xor_sync(0xffffffffu, v, o);
    return v;
}
__device__ __forceinline__ float warp_max(float v) {
#pragma unroll
    for (int o = 16; o; o >>= 1) v = fmaxf(v, __shfl_xor_sync(0xffffffffu, v, o));
    return v;
}
__device__ __forceinline__ float dot4(float4 a, float4 b) {
    return fmaf(a.x, b.x, fmaf(a.y, b.y, fmaf(a.z, b.z, a.w * b.w)));
}

// ---------------- K1: weight-stationary GEMV, 4 outputs/block, all 32 batches
__global__ __launch_bounds__(256) void k1_ht(const float* __restrict__ src,
                                             const float* __restrict__ Win) {
    int o0 = blockIdx.x * 4;
    int t = threadIdx.x, wid = t >> 5, lane = t & 31;
    __shared__ float row[4][D];           // 8 KB
    const float4* W4 = (const float4*)(Win + (size_t)o0 * D);
    float4* r4 = (float4*)row;
    r4[t] = W4[t];
    r4[t + 256] = W4[t + 256];
    __syncthreads();
    int b0 = wid * 4;
#pragma unroll
    for (int bb = 0; bb < 4; bb++) {
        int b = b0 + bb;
        const float4* x4 = (const float4*)(src + (size_t)b * D);
        float4 xv[4];
#pragma unroll
        for (int j = 0; j < 4; j++) xv[j] = x4[lane + j * 32];
#pragma unroll
        for (int o = 0; o < 4; o++) {
            const float4* rr = (const float4*)row[o];
            float p = 0.f;
#pragma unroll
            for (int j = 0; j < 4; j++) p += dot4(rr[lane + j * 32], xv[j]);
            p = warp_sum(p);
            if (lane == 0) g_ht[(size_t)b * D + o0 + o] = p;
        }
    }
}

// per-row score + online-softmax update (all lanes see sc via butterfly)
#define DOROW(IDX, V0, V1, V2, V3)                                          \
    {                                                                       \
        float p = dot4(V0, h0) + dot4(V1, h1) + dot4(V2, h2) + dot4(V3, h3);\
        float sc = warp_sum(p);                                             \
        if (lane == 0) g_scores[b * S + s0 + (IDX)] = sc;                   \
        float mn = fmaxf(m, sc);                                            \
        float scale = __expf(m - mn);                                       \
        float w = __expf(sc - mn);                                          \
        l = fmaf(l, scale, w);                                              \
        c0.x = fmaf(w, V0.x, scale * c0.x); c0.y = fmaf(w, V0.y, scale * c0.y); \
        c0.z = fmaf(w, V0.z, scale * c0.z); c0.w = fmaf(w, V0.w, scale * c0.w); \
        c1.x = fmaf(w, V1.x, scale * c1.x); c1.y = fmaf(w, V1.y, scale * c1.y); \
        c1.z = fmaf(w, V1.z, scale * c1.z); c1.w = fmaf(w, V1.w, scale * c1.w); \
        c2.x = fmaf(w, V2.x, scale * c2.x); c2.y = fmaf(w, V2.y, scale * c2.y); \
        c2.z = fmaf(w, V2.z, scale * c2.z); c2.w = fmaf(w, V2.w, scale * c2.w); \
        c3.x = fmaf(w, V3.x, scale * c3.x); c3.y = fmaf(w, V3.y, scale * c3.y); \
        c3.z = fmaf(w, V3.z, scale * c3.z); c3.w = fmaf(w, V3.w, scale * c3.w); \
        m = mn;                                                             \
    }

#define LOADROW(P0, P1, P2, P3, IDX)                                        \
    {                                                                       \
        const float4* rn = r + (size_t)(IDX) * 128;                         \
        P0 = rn[0]; P1 = rn[32]; P2 = rn[64]; P3 = rn[96];                  \
    }

// ---------------- K2: single pass over memory_bank with depth-2 pipeline
__global__ __launch_bounds__(256, 2) void k2_stream(const float* __restrict__ mb,
                                                    const void* __restrict__ lens) {
    int chunk = blockIdx.x, b = blockIdx.y;
    int t = threadIdx.x, wid = t >> 5, lane = t & 31;
    int len = get_len(lens, b);
    int s0 = chunk * CHUNK + wid * PPW;

    const float4* h4 = (const float4*)(g_ht + b * D);
    float4 h0 = h4[lane], h1 = h4[lane + 32], h2 = h4[lane + 64], h3 = h4[lane + 96];

    float m = NEG_BIG, l = 0.f;
    float4 c0 = {0, 0, 0, 0}, c1 = {0, 0, 0, 0}, c2 = {0, 0, 0, 0}, c3 = {0, 0, 0, 0};

    int nv = len - s0;
    nv = nv < 0 ? 0 : (nv > PPW ? PPW : nv);

    const float4* r = (const float4*)mb + ((size_t)b * S + s0) * 128 + lane;
    if (nv > 0) {
        float4 A0, A1, A2, A3, B0, B1, B2, B3;
        LOADROW(A0, A1, A2, A3, 0);
        if (nv > 1) LOADROW(B0, B1, B2, B3, 1);
        int i = 0;
        for (; i + 1 < nv; i += 2) {
            float4 v0 = A0, v1 = A1, v2 = A2, v3 = A3;
            if (i + 2 < nv) LOADROW(A0, A1, A2, A3, i + 2);
            DOROW(i, v0, v1, v2, v3);
            float4 u0 = B0, u1 = B1, u2 = B2, u3 = B3;
            if (i + 3 < nv) LOADROW(B0, B1, B2, B3, i + 3);
            DOROW(i + 1, u0, u1, u2, u3);
        }
        if (i < nv) DOROW(i, A0, A1, A2, A3);
    }
    // masked tail: sentinel scores (normalizer maps these to exact 0)
    for (int j = nv + lane; j < PPW; j += 32)
        g_scores[b * S + s0 + j] = NEG_BIG;

    // ---- block merge of the 8 warps ----
    __shared__ float sm_m[K2_WARPS], sm_l[K2_WARPS], sm_f[K2_WARPS];
    __shared__ float sm_c[K2_WARPS * D];
    if (lane == 0) { sm_m[wid] = m; sm_l[wid] = l; }
    float4* cw = (float4*)(sm_c + wid * D);
    cw[lane] = c0; cw[lane + 32] = c1; cw[lane + 64] = c2; cw[lane + 96] = c3;
    __syncthreads();
    if (t == 0) {
        float Mb = NEG_BIG;
#pragma unroll
        for (int w2 = 0; w2 < K2_WARPS; w2++) Mb = fmaxf(Mb, sm_m[w2]);
        float Lb = 0.f;
#pragma unroll
        for (int w2 = 0; w2 < K2_WARPS; w2++) {
            float f = __expf(sm_m[w2] - Mb);
            sm_f[w2] = f;
            Lb = fmaf(sm_l[w2], f, Lb);
        }
        g_pm[b * CPB + chunk] = Mb;
        g_pl[b * CPB + chunk] = Lb;
    }
    __syncthreads();
    for (int d = t; d < D; d += 256) {
        float acc = 0.f;
#pragma unroll
        for (int w2 = 0; w2 < K2_WARPS; w2++) acc = fmaf(sm_f[w2], sm_c[w2 * D + d], acc);
        g_pc[((size_t)b * CPB + chunk) * D + d] = acc;
    }
}

// ---------------- K3a: per-batch M, 1/L, chunk factors (one warp per batch)
__global__ void k3a_stats() {
    int b = blockIdx.x, lane = threadIdx.x;
    float pm = g_pm[b * CPB + lane];
    float pl = g_pl[b * CPB + lane];
    float M = warp_max(pm);
    float f = __expf(pm - M);
    float L = warp_sum(pl * f);
    g_fac[b * CPB + lane] = f;
    if (lane == 0) { g_stat[b * 2] = M; g_stat[b * 2 + 1] = 1.f / L; }
}

// ---------------- K3b: y==0 combine c + build concat; y in 1..8 align output
__global__ __launch_bounds__(256) void k3b_finish(const float* __restrict__ src,
                                                  float* __restrict__ out) {
    int b = blockIdx.x, y = blockIdx.y, t = threadIdx.x;
    float invL = g_stat[b * 2 + 1];
    if (y == 0) {
        __shared__ float sf[CPB];
        if (t < CPB) sf[t] = g_fac[b * CPB + t];
        __syncthreads();
        for (int d = t; d < D; d += 256) {
            float acc = 0.f;
#pragma unroll
            for (int i = 0; i < CPB; i++)
                acc = fmaf(sf[i], g_pc[((size_t)b * CPB + i) * D + d], acc);
            g_cat[(size_t)b * 2 * D + d] = acc * invL;
        }
        for (int d = t; d < D; d += 256)
            g_cat[(size_t)b * 2 * D + D + d] = src[(size_t)b * D + d];
    } else {
        float M = g_stat[b * 2];
        int s0 = (y - 1) * 512;
        float* oal = out + (size_t)B * D + (size_t)b * S;
        for (int s = s0 + t; s < s0 + 512; s += 256)
            oal[s] = __expf(g_scores[b * S + s] - M) * invL;
    }
}

// ---------------- K4: weight-stationary GEMV over W_out, 4 outputs/block
__global__ __launch_bounds__(256) void k4_out(const float* __restrict__ Wout,
                                              float* __restrict__ out) {
    int o0 = blockIdx.x * 4;
    int t = threadIdx.x, wid = t >> 5, lane = t & 31;
    __shared__ float row[4][2 * D];       // 16 KB
    const float4* W4 = (const float4*)(Wout + (size_t)o0 * 2 * D);
    float4* r4 = (float4*)row;
#pragma unroll
    for (int j = 0; j < 4; j++) r4[t + j * 256] = W4[t + j * 256];
    __syncthreads();
    int b0 = wid * 4;
#pragma unroll
    for (int bb = 0; bb < 4; bb++) {
        int b = b0 + bb;
        const float4* x4 = (const float4*)(g_cat + (size_t)b * 2 * D);
        float4 xv[8];
#pragma unroll
        for (int j = 0; j < 8; j++) xv[j] = x4[lane + j * 32];
#pragma unroll
        for (int o = 0; o < 4; o++) {
            const float4* rr = (const float4*)row[o];
            float p = 0.f;
#pragma unroll
            for (int j = 0; j < 8; j++) p += dot4(rr[lane + j * 32], xv[j]);
            p = warp_sum(p);
            if (lane == 0) out[(size_t)b * D + o0 + o] = p;
        }
    }
}

extern "C" void kernel_launch(void* const* d_in, const int* in_sizes, int n_in,
                              void* d_out, int out_size) {
    const float* src  = (const float*)d_in[0];  // source [B,1,D]
    const float* mb   = (const float*)d_in[1];  // memory_bank [B,S,D]
    const void*  lens = d_in[2];                // memory_lengths [B]
    const float* Win  = (const float*)d_in[3];  // [D, D]
    const float* Wout = (const float*)d_in[4];  // [D, 2D]
    float* out = (float*)d_out;                 // [B*D attn_h | B*S align]

    k1_ht<<<D / 4, 256>>>(src, Win);
    dim3 g2(CPB, B);
    k2_stream<<<g2, 256>>>(mb, lens);
    k3a_stats<<<B, 32>>>();
    dim3 g3(B, 9);
    k3b_finish<<<g3, 256>>>(src, out);
    k4_out<<<D / 4, 256>>>(Wout, out);
}

// round 5
// speedup vs baseline: 3.0949x; 1.0454x over previous
#include <cuda_runtime.h>
#include <math.h>

#define B 32
#define S 4096
#define D 512
#define CPB 32            // chunks per batch
#define CHUNK 128         // S / CPB
#define K2_WARPS 8
#define PPW 16            // rows per warp in k2
#define NEG_BIG (-1e30f)

// ---------------- scratch (no allocations allowed) ----------------
__device__ float g_ht[B * D];            // h_t = source @ W_in^T
__device__ float g_scores[B * S];        // raw (unnormalized) scores
__device__ float g_pm[B * CPB];          // per-chunk max
__device__ float g_pl[B * CPB];          // per-chunk exp-sum (rel. to chunk max)
__device__ float g_pc[B * CPB * D];      // per-chunk weighted context partial
__device__ float g_cat[B * 2 * D];       // [c | source] concat per batch

// memory_lengths may arrive as int32 (JAX x64 off) or int64.
// lengths in [S/2, S]; int64 view of elem 0 is in-range iff data truly int64.
__device__ __forceinline__ int get_len(const void* p, int b) {
    long long v0 = ((const long long*)p)[0];
    if (v0 >= 0 && v0 <= (long long)S) return (int)((const long long*)p)[b];
    return ((const int*)p)[b];
}

__device__ __forceinline__ float warp_sum(float v) {
#pragma unroll
    for (int o = 16; o; o >>= 1) v += __shfl_xor_sync(0xffffffffu, v, o);
    return v;
}
__device__ __forceinline__ float warp_max(float v) {
#pragma unroll
    for (int o = 16; o; o >>= 1) v = fmaxf(v, __shfl_xor_sync(0xffffffffu, v, o));
    return v;
}
__device__ __forceinline__ float dot4(float4 a, float4 b) {
    return fmaf(a.x, b.x, fmaf(a.y, b.y, fmaf(a.z, b.z, a.w * b.w)));
}

// ---------------- K1: weight-stationary GEMV, 4 outputs/block, all 32 batches
__global__ __launch_bounds__(256) void k1_ht(const float* __restrict__ src,
                                             const float* __restrict__ Win) {
    int o0 = blockIdx.x * 4;
    int t = threadIdx.x, wid = t >> 5, lane = t & 31;
    __shared__ float row[4][D];           // 8 KB
    const float4* W4 = (const float4*)(Win + (size_t)o0 * D);
    float4* r4 = (float4*)row;
    r4[t] = W4[t];
    r4[t + 256] = W4[t + 256];
    __syncthreads();
    int b0 = wid * 4;
#pragma unroll
    for (int bb = 0; bb < 4; bb++) {
        int b = b0 + bb;
        const float4* x4 = (const float4*)(src + (size_t)b * D);
        float4 xv[4];
#pragma unroll
        for (int j = 0; j < 4; j++) xv[j] = x4[lane + j * 32];
#pragma unroll
        for (int o = 0; o < 4; o++) {
            const float4* rr = (const float4*)row[o];
            float p = 0.f;
#pragma unroll
            for (int j = 0; j < 4; j++) p += dot4(rr[lane + j * 32], xv[j]);
            p = warp_sum(p);
            if (lane == 0) g_ht[(size_t)b * D + o0 + o] = p;
        }
    }
}

// per-row score + online-softmax update
#define DOROW(IDX, V0, V1, V2, V3)                                          \
    {                                                                       \
        float p = dot4(V0, h0) + dot4(V1, h1) + dot4(V2, h2) + dot4(V3, h3);\
        float sc = warp_sum(p);                                             \
        if (lane == 0) g_scores[b * S + s0 + (IDX)] = sc;                   \
        float mn = fmaxf(m, sc);                                            \
        float scale = __expf(m - mn);                                       \
        float w = __expf(sc - mn);                                          \
        l = fmaf(l, scale, w);                                              \
        c0.x = fmaf(w, V0.x, scale * c0.x); c0.y = fmaf(w, V0.y, scale * c0.y); \
        c0.z = fmaf(w, V0.z, scale * c0.z); c0.w = fmaf(w, V0.w, scale * c0.w); \
        c1.x = fmaf(w, V1.x, scale * c1.x); c1.y = fmaf(w, V1.y, scale * c1.y); \
        c1.z = fmaf(w, V1.z, scale * c1.z); c1.w = fmaf(w, V1.w, scale * c1.w); \
        c2.x = fmaf(w, V2.x, scale * c2.x); c2.y = fmaf(w, V2.y, scale * c2.y); \
        c2.z = fmaf(w, V2.z, scale * c2.z); c2.w = fmaf(w, V2.w, scale * c2.w); \
        c3.x = fmaf(w, V3.x, scale * c3.x); c3.y = fmaf(w, V3.y, scale * c3.y); \
        c3.z = fmaf(w, V3.z, scale * c3.z); c3.w = fmaf(w, V3.w, scale * c3.w); \
        m = mn;                                                             \
    }

#define LOADROW(P0, P1, P2, P3, IDX)                                        \
    {                                                                       \
        const float4* rn = r + (size_t)(IDX) * 128;                         \
        P0 = rn[0]; P1 = rn[32]; P2 = rn[64]; P3 = rn[96];                  \
    }

// process row I from ring slot (PA*); prefetch row I+3 into the same slot
#define STEP3(I, PA0, PA1, PA2, PA3)                                        \
    {                                                                       \
        float4 t0 = PA0, t1 = PA1, t2 = PA2, t3 = PA3;                      \
        if ((I) + 3 < PPW) LOADROW(PA0, PA1, PA2, PA3, (I) + 3);            \
        DOROW(I, t0, t1, t2, t3);                                           \
    }

// ---------------- K2: single pass over memory_bank, online softmax
__global__ __launch_bounds__(256, 2) void k2_stream(const float* __restrict__ mb,
                                                    const void* __restrict__ lens) {
    int chunk = blockIdx.x, b = blockIdx.y;
    int t = threadIdx.x, wid = t >> 5, lane = t & 31;
    int len = get_len(lens, b);
    int s0 = chunk * CHUNK + wid * PPW;

    const float4* h4 = (const float4*)(g_ht + b * D);
    float4 h0 = h4[lane], h1 = h4[lane + 32], h2 = h4[lane + 64], h3 = h4[lane + 96];

    float m = NEG_BIG, l = 0.f;
    float4 c0 = {0, 0, 0, 0}, c1 = {0, 0, 0, 0}, c2 = {0, 0, 0, 0}, c3 = {0, 0, 0, 0};

    int nv = len - s0;
    nv = nv < 0 ? 0 : (nv > PPW ? PPW : nv);

    const float4* r = (const float4*)mb + ((size_t)b * S + s0) * 128 + lane;
    if (nv == PPW) {
        // common case: full 16 rows, depth-3 pipelined, fully unrolled
        float4 p00, p01, p02, p03, p10, p11, p12, p13, p20, p21, p22, p23;
        LOADROW(p00, p01, p02, p03, 0);
        LOADROW(p10, p11, p12, p13, 1);
        LOADROW(p20, p21, p22, p23, 2);
        STEP3(0,  p00, p01, p02, p03);
        STEP3(1,  p10, p11, p12, p13);
        STEP3(2,  p20, p21, p22, p23);
        STEP3(3,  p00, p01, p02, p03);
        STEP3(4,  p10, p11, p12, p13);
        STEP3(5,  p20, p21, p22, p23);
        STEP3(6,  p00, p01, p02, p03);
        STEP3(7,  p10, p11, p12, p13);
        STEP3(8,  p20, p21, p22, p23);
        STEP3(9,  p00, p01, p02, p03);
        STEP3(10, p10, p11, p12, p13);
        STEP3(11, p20, p21, p22, p23);
        STEP3(12, p00, p01, p02, p03);
        STEP3(13, p10, p11, p12, p13);
        STEP3(14, p20, p21, p22, p23);
        STEP3(15, p00, p01, p02, p03);
    } else if (nv > 0) {
        // boundary chunk: generic depth-2 loop
        float4 A0, A1, A2, A3, B0, B1, B2, B3;
        LOADROW(A0, A1, A2, A3, 0);
        if (nv > 1) LOADROW(B0, B1, B2, B3, 1);
        int i = 0;
        for (; i + 1 < nv; i += 2) {
            float4 v0 = A0, v1 = A1, v2 = A2, v3 = A3;
            if (i + 2 < nv) LOADROW(A0, A1, A2, A3, i + 2);
            DOROW(i, v0, v1, v2, v3);
            float4 u0 = B0, u1 = B1, u2 = B2, u3 = B3;
            if (i + 3 < nv) LOADROW(B0, B1, B2, B3, i + 3);
            DOROW(i + 1, u0, u1, u2, u3);
        }
        if (i < nv) DOROW(i, A0, A1, A2, A3);
    }
    // masked tail: sentinel scores (normalizer maps these to exact 0)
    for (int j = nv + lane; j < PPW; j += 32)
        g_scores[b * S + s0 + j] = NEG_BIG;

    // ---- block merge of the 8 warps ----
    __shared__ float sm_m[K2_WARPS], sm_l[K2_WARPS], sm_f[K2_WARPS];
    __shared__ float sm_c[K2_WARPS * D];
    if (lane == 0) { sm_m[wid] = m; sm_l[wid] = l; }
    float4* cw = (float4*)(sm_c + wid * D);
    cw[lane] = c0; cw[lane + 32] = c1; cw[lane + 64] = c2; cw[lane + 96] = c3;
    __syncthreads();
    if (t == 0) {
        float Mb = NEG_BIG;
#pragma unroll
        for (int w2 = 0; w2 < K2_WARPS; w2++) Mb = fmaxf(Mb, sm_m[w2]);
        float Lb = 0.f;
#pragma unroll
        for (int w2 = 0; w2 < K2_WARPS; w2++) {
            float f = __expf(sm_m[w2] - Mb);
            sm_f[w2] = f;
            Lb = fmaf(sm_l[w2], f, Lb);
        }
        g_pm[b * CPB + chunk] = Mb;
        g_pl[b * CPB + chunk] = Lb;
    }
    __syncthreads();
    for (int d = t; d < D; d += 256) {
        float acc = 0.f;
#pragma unroll
        for (int w2 = 0; w2 < K2_WARPS; w2++) acc = fmaf(sm_f[w2], sm_c[w2 * D + d], acc);
        g_pc[((size_t)b * CPB + chunk) * D + d] = acc;
    }
}

// ---------------- K3: fused stats + combine + align output
// grid (B, 5): y==0 -> combine c and build concat; y in 1..4 -> align (1024 scores each)
__global__ __launch_bounds__(256) void k3_all(const float* __restrict__ src,
                                              float* __restrict__ out) {
    int b = blockIdx.x, y = blockIdx.y, t = threadIdx.x;
    __shared__ float sf[CPB];
    __shared__ float sM, sInv;
    if (t < 32) {
        float pm = g_pm[b * CPB + t];
        float pl = g_pl[b * CPB + t];
        float M = warp_max(pm);
        float f = __expf(pm - M);
        float L = warp_sum(pl * f);
        sf[t] = f;
        if (t == 0) { sM = M; sInv = 1.f / L; }
    }
    __syncthreads();
    if (y == 0) {
        float invL = sInv;
        if (t < 128) {
            // combine: 128 threads x float4 = 512 d-values, 32 unrolled partials
            const float4* pc = (const float4*)g_pc + (size_t)b * CPB * 128 + t;
            float4 acc = {0, 0, 0, 0};
#pragma unroll
            for (int i = 0; i < CPB; i++) {
                float4 v = pc[i * 128];
                float f = sf[i];
                acc.x = fmaf(f, v.x, acc.x);
                acc.y = fmaf(f, v.y, acc.y);
                acc.z = fmaf(f, v.z, acc.z);
                acc.w = fmaf(f, v.w, acc.w);
            }
            acc.x *= invL; acc.y *= invL; acc.z *= invL; acc.w *= invL;
            ((float4*)(g_cat + (size_t)b * 2 * D))[t] = acc;
        } else {
            // copy source into concat's second half
            int d = t - 128;
            ((float4*)(g_cat + (size_t)b * 2 * D + D))[d] =
                ((const float4*)(src + (size_t)b * D))[d];
        }
    } else {
        float M = sM, invL = sInv;
        int s0 = (y - 1) * 1024;
        const float4* sc4 = (const float4*)(g_scores + (size_t)b * S + s0);
        float4* o4 = (float4*)(out + (size_t)B * D + (size_t)b * S + s0);
        float4 v = sc4[t];
        float4 rr;
        rr.x = __expf(v.x - M) * invL;
        rr.y = __expf(v.y - M) * invL;
        rr.z = __expf(v.z - M) * invL;
        rr.w = __expf(v.w - M) * invL;
        o4[t] = rr;
    }
}

// ---------------- K4: weight-stationary GEMV over W_out, 4 outputs/block
__global__ __launch_bounds__(256) void k4_out(const float* __restrict__ Wout,
                                              float* __restrict__ out) {
    int o0 = blockIdx.x * 4;
    int t = threadIdx.x, wid = t >> 5, lane = t & 31;
    __shared__ float row[4][2 * D];       // 16 KB
    const float4* W4 = (const float4*)(Wout + (size_t)o0 * 2 * D);
    float4* r4 = (float4*)row;
#pragma unroll
    for (int j = 0; j < 4; j++) r4[t + j * 256] = W4[t + j * 256];
    __syncthreads();
    int b0 = wid * 4;
#pragma unroll
    for (int bb = 0; bb < 4; bb++) {
        int b = b0 + bb;
        const float4* x4 = (const float4*)(g_cat + (size_t)b * 2 * D);
        float4 xv[8];
#pragma unroll
        for (int j = 0; j < 8; j++) xv[j] = x4[lane + j * 32];
#pragma unroll
        for (int o = 0; o < 4; o++) {
            const float4* rr = (const float4*)row[o];
            float p = 0.f;
#pragma unroll
            for (int j = 0; j < 8; j++) p += dot4(rr[lane + j * 32], xv[j]);
            p = warp_sum(p);
            if (lane == 0) out[(size_t)b * D + o0 + o] = p;
        }
    }
}

extern "C" void kernel_launch(void* const* d_in, const int* in_sizes, int n_in,
                              void* d_out, int out_size) {
    const float* src  = (const float*)d_in[0];  // source [B,1,D]
    const float* mb   = (const float*)d_in[1];  // memory_bank [B,S,D]
    const void*  lens = d_in[2];                // memory_lengths [B]
    const float* Win  = (const float*)d_in[3];  // [D, D]
    const float* Wout = (const float*)d_in[4];  // [D, 2D]
    float* out = (float*)d_out;                 // [B*D attn_h | B*S align]

    k1_ht<<<D / 4, 256>>>(src, Win);
    dim3 g2(CPB, B);
    k2_stream<<<g2, 256>>>(mb, lens);
    dim3 g3(B, 5);
    k3_all<<<g3, 256>>>(src, out);
    k4_out<<<D / 4, 256>>>(Wout, out);
}